// round 2
// baseline (speedup 1.0000x reference)
#include <cuda_runtime.h>
#include <math.h>
#include <stdint.h>

#define BATCH   64
#define TLEN    2048
#define DI      256
#define DO      256
#define DS      512
#define NP      256
#define NF      768
#define BT      (BATCH*TLEN)
#define CHUNK   128
#define NCHUNK  (TLEN/CHUNK)
#define NSQ     14

__device__ float  g_Kfull[NF*NF];
__device__ float  g_M0[NF*NF];
__device__ float  g_M1[NF*NF];
__device__ float  g_scale;
__device__ double g_L;
__device__ float  g_bscale, g_cscale, g_dscale;
__device__ float2 g_lam[NP];
__device__ float2 g_chunkend[BATCH*NCHUNK*NP];
__device__ float2 g_carry[BATCH*NCHUNK*NP];
__device__ float  g_W[67108864];   // 131072 x 512

// Build K_raw = [[K11(rot), K12],[K21, K22]]
__global__ void build_kernel(const float* __restrict__ rho_raw,
                             const float* __restrict__ theta,
                             const float* __restrict__ K12,
                             const float* __restrict__ K21,
                             const float* __restrict__ K22) {
    int idx = blockIdx.x * blockDim.x + threadIdx.x;
    if (idx >= NF*NF) return;
    int r = idx / NF, c = idx % NF;
    float v;
    if (r < DS) {
        if (c < DS) {
            v = 0.f;
            int p = r >> 1;
            if ((c >> 1) == p) {
                float rho = (1.f / (1.f + expf(-rho_raw[p]))) * 0.999f;
                float rc = rho * cosf(theta[p]);
                float rs = rho * sinf(theta[p]);
                if ((r & 1) == 0) v = (c == r) ? rc : -rs;
                else              v = (c == r) ? rc :  rs;
            }
        } else v = K12[(size_t)r * DI + (c - DS)];
    } else {
        if (c < DS) v = K21[(size_t)(r - DS) * DS + c];
        else        v = K22[(size_t)(r - DS) * DI + (c - DS)];
    }
    g_Kfull[idx] = v;
}

// M0 = K^T K  (64x64 tiles, BK=16, 256 threads, 4x4 micro)
__global__ void ktk_kernel() {
    __shared__ __align__(16) float As[16][68];
    __shared__ __align__(16) float Bs[16][68];
    int tid = threadIdx.x;
    int m0 = blockIdx.y * 64, n0 = blockIdx.x * 64;
    int lk = tid >> 4, lq = (tid & 15) << 2;
    int ty = tid >> 4, tx = tid & 15;
    float acc[4][4] = {};
    for (int k0 = 0; k0 < NF; k0 += 16) {
        float4 a = *(const float4*)&g_Kfull[(size_t)(k0 + lk) * NF + m0 + lq];
        float4 b = *(const float4*)&g_Kfull[(size_t)(k0 + lk) * NF + n0 + lq];
        __syncthreads();
        *(float4*)&As[lk][lq] = a;
        *(float4*)&Bs[lk][lq] = b;
        __syncthreads();
#pragma unroll
        for (int kk = 0; kk < 16; kk++) {
            float4 av = *(const float4*)&As[kk][ty << 2];
            float4 bv = *(const float4*)&Bs[kk][tx << 2];
            float A4[4] = {av.x, av.y, av.z, av.w};
            float B4[4] = {bv.x, bv.y, bv.z, bv.w};
#pragma unroll
            for (int i = 0; i < 4; i++)
#pragma unroll
                for (int j = 0; j < 4; j++) acc[i][j] += A4[i] * B4[j];
        }
    }
#pragma unroll
    for (int i = 0; i < 4; i++) {
        float4 o = {acc[i][0], acc[i][1], acc[i][2], acc[i][3]};
        *(float4*)&g_M0[(size_t)(m0 + (ty << 2) + i) * NF + n0 + (tx << 2)] = o;
    }
}

// t_k = tr(B_k); g_scale = 1/t_k; L_{k+1} = 2(L_k + ln t_k)
__global__ void trace_kernel(int k) {
    const float* src = (k & 1) ? g_M1 : g_M0;
    __shared__ double red[1024];
    int i = threadIdx.x;
    red[i] = (i < NF) ? (double)src[(size_t)i * NF + i] : 0.0;
    __syncthreads();
    for (int s = 512; s > 0; s >>= 1) {
        if (i < s) red[i] += red[i + s];
        __syncthreads();
    }
    if (i == 0) {
        double t = red[0];
        double L = (k == 0) ? 0.0 : g_L;
        g_L = 2.0 * (L + log(t));
        g_scale = (float)(1.0 / t);
    }
}

// B_{k+1} = (B_k * g_scale)^2
__global__ void sq_kernel(int k) {
    const float* src = (k & 1) ? g_M1 : g_M0;
    float*       dst = (k & 1) ? g_M0 : g_M1;
    __shared__ __align__(16) float As[16][68];
    __shared__ __align__(16) float Bs[16][68];
    int tid = threadIdx.x;
    int m0 = blockIdx.y * 64, n0 = blockIdx.x * 64;
    int am = tid >> 2, akq = (tid & 3) << 2;
    int lk = tid >> 4, lq = (tid & 15) << 2;
    int ty = tid >> 4, tx = tid & 15;
    float acc[4][4] = {};
    for (int k0 = 0; k0 < NF; k0 += 16) {
        float4 a = *(const float4*)&src[(size_t)(m0 + am) * NF + k0 + akq];
        float4 b = *(const float4*)&src[(size_t)(k0 + lk) * NF + n0 + lq];
        __syncthreads();
        As[akq + 0][am] = a.x; As[akq + 1][am] = a.y;
        As[akq + 2][am] = a.z; As[akq + 3][am] = a.w;
        *(float4*)&Bs[lk][lq] = b;
        __syncthreads();
#pragma unroll
        for (int kk = 0; kk < 16; kk++) {
            float4 av = *(const float4*)&As[kk][ty << 2];
            float4 bv = *(const float4*)&Bs[kk][tx << 2];
            float A4[4] = {av.x, av.y, av.z, av.w};
            float B4[4] = {bv.x, bv.y, bv.z, bv.w};
#pragma unroll
            for (int i = 0; i < 4; i++)
#pragma unroll
                for (int j = 0; j < 4; j++) acc[i][j] += A4[i] * B4[j];
        }
    }
    float s = g_scale, s2 = s * s;
#pragma unroll
    for (int i = 0; i < 4; i++) {
        float4 o = {acc[i][0]*s2, acc[i][1]*s2, acc[i][2]*s2, acc[i][3]*s2};
        *(float4*)&dst[(size_t)(m0 + (ty << 2) + i) * NF + n0 + (tx << 2)] = o;
    }
}

__global__ void finalize_kernel(const float* __restrict__ rho_raw,
                                const float* __restrict__ theta,
                                const float* __restrict__ log_gamma) {
    __shared__ double red[256];
    __shared__ float sh_inv;
    int i = threadIdx.x;
    double s = 0.0;
    for (int j = i; j < NF; j += 256) s += (double)g_M0[(size_t)j * NF + j];
    red[i] = s;
    __syncthreads();
    for (int st = 128; st > 0; st >>= 1) {
        if (i < st) red[i] += red[i + st];
        __syncthreads();
    }
    if (i == 0) {
        double lnl = (log(red[0]) + g_L) / 16384.0;
        double sig = exp(0.5 * lnl);
        if (sig < 1e-5) sig = 1e-5;
        double inv = 1.0 / (sig + 0.002);
        float gam = expf(log_gamma[0]);
        sh_inv = (float)inv;
        g_bscale = gam * (float)inv;
        g_cscale = (float)inv;
        g_dscale = gam * (float)inv;
    }
    __syncthreads();
    float inv = sh_inv;
    float rho = (1.f / (1.f + expf(-rho_raw[i]))) * 0.999f;
    float th = theta[i];
    g_lam[i] = make_float2(rho * cosf(th) * inv, rho * sinf(th) * inv);
}

// W[m,n] = bscale * sum_k u[m,k] * K12[n,k]   (128x128x8, 8x8 micro)
__global__ void __launch_bounds__(256) bu_gemm_kernel(const float* __restrict__ u,
                                                      const float* __restrict__ K12) {
    __shared__ __align__(16) float As[8][132];
    __shared__ __align__(16) float Bs[8][132];
    int tid = threadIdx.x;
    size_t m0 = (size_t)blockIdx.y * 128;
    int n0 = blockIdx.x * 128;
    int lm = tid >> 1, lk = (tid & 1) << 2;
    int ty = tid >> 4, tx = tid & 15;
    float acc[8][8] = {};
    for (int k0 = 0; k0 < DI; k0 += 8) {
        float4 a = *(const float4*)&u[(m0 + lm) * DI + k0 + lk];
        float4 b = *(const float4*)&K12[(size_t)(n0 + lm) * DI + k0 + lk];
        __syncthreads();
        As[lk+0][lm]=a.x; As[lk+1][lm]=a.y; As[lk+2][lm]=a.z; As[lk+3][lm]=a.w;
        Bs[lk+0][lm]=b.x; Bs[lk+1][lm]=b.y; Bs[lk+2][lm]=b.z; Bs[lk+3][lm]=b.w;
        __syncthreads();
#pragma unroll
        for (int kk = 0; kk < 8; kk++) {
            float4 a0 = *(const float4*)&As[kk][ty << 3];
            float4 a1 = *(const float4*)&As[kk][(ty << 3) + 4];
            float4 b0 = *(const float4*)&Bs[kk][tx << 3];
            float4 b1 = *(const float4*)&Bs[kk][(tx << 3) + 4];
            float Av[8] = {a0.x,a0.y,a0.z,a0.w,a1.x,a1.y,a1.z,a1.w};
            float Bv[8] = {b0.x,b0.y,b0.z,b0.w,b1.x,b1.y,b1.z,b1.w};
#pragma unroll
            for (int i = 0; i < 8; i++)
#pragma unroll
                for (int j = 0; j < 8; j++) acc[i][j] += Av[i] * Bv[j];
        }
    }
    float sc = g_bscale;
#pragma unroll
    for (int i = 0; i < 8; i++) {
        size_t row = m0 + (ty << 3) + i;
        float4 o0 = {acc[i][0]*sc, acc[i][1]*sc, acc[i][2]*sc, acc[i][3]*sc};
        float4 o1 = {acc[i][4]*sc, acc[i][5]*sc, acc[i][6]*sc, acc[i][7]*sc};
        *(float4*)&g_W[row * DS + n0 + (tx << 3)]     = o0;
        *(float4*)&g_W[row * DS + n0 + (tx << 3) + 4] = o1;
    }
}

// local scan: writes pre-state in place, records chunk-end state
__global__ void scan_kernel() {
    int p = threadIdx.x, c = blockIdx.x, b = blockIdx.y;
    float2 lam = g_lam[p];
    float2* W2 = (float2*)g_W;
    size_t base = ((size_t)(b * TLEN + c * CHUNK)) * NP + p;
    float2 w = make_float2(0.f, 0.f);
    for (int j = 0; j < CHUNK; j++) {
        float2 bu = W2[base + (size_t)j * NP];
        W2[base + (size_t)j * NP] = w;
        float nx = lam.x * w.x - lam.y * w.y + bu.x;
        float ny = lam.x * w.y + lam.y * w.x + bu.y;
        w.x = nx; w.y = ny;
    }
    g_chunkend[(b * NCHUNK + c) * NP + p] = w;
}

// carry: z_{(c+1)L} = end(c) + lam^CHUNK * z_{cL}
__global__ void carry_kernel() {
    int p = threadIdx.x, b = blockIdx.x;
    float2 m = g_lam[p];
#pragma unroll
    for (int i = 0; i < 7; i++) {   // lam^128
        float mx = m.x * m.x - m.y * m.y;
        m.y = 2.f * m.x * m.y;
        m.x = mx;
    }
    float2 zc = make_float2(0.f, 0.f);
    for (int c = 0; c < NCHUNK; c++) {
        g_carry[(b * NCHUNK + c) * NP + p] = zc;
        float2 e = g_chunkend[(b * NCHUNK + c) * NP + p];
        float zx = e.x + m.x * zc.x - m.y * zc.y;
        float zy = e.y + m.x * zc.y + m.y * zc.x;
        zc.x = zx; zc.y = zy;
    }
}

// fixup: z_t += lam^j * carry (early exit once decayed)
__global__ void fixup_kernel() {
    int p = threadIdx.x, c = blockIdx.x, b = blockIdx.y;
    float2 zc = g_carry[(b * NCHUNK + c) * NP + p];
    float2 lam = g_lam[p];
    float2* W2 = (float2*)g_W;
    size_t base = ((size_t)(b * TLEN + c * CHUNK)) * NP + p;
    for (int j = 0; j < CHUNK; j++) {
        if (zc.x * zc.x + zc.y * zc.y <= 1e-32f) break;
        float2 w = W2[base + (size_t)j * NP];
        w.x += zc.x; w.y += zc.y;
        W2[base + (size_t)j * NP] = w;
        float zx = lam.x * zc.x - lam.y * zc.y;
        float zy = lam.x * zc.y + lam.y * zc.x;
        zc.x = zx; zc.y = zy;
    }
}

// y[m,o] = sum_{k<512} W[m,k]*csc*K21[o,k] + sum_{k<256} u[m,k]*dsc*K22[o,k]
__global__ void __launch_bounds__(256) y_gemm_kernel(const float* __restrict__ u,
                                                     const float* __restrict__ K21,
                                                     const float* __restrict__ K22,
                                                     float* __restrict__ y) {
    __shared__ __align__(16) float As[8][132];
    __shared__ __align__(16) float Bs[8][132];
    int tid = threadIdx.x;
    size_t m0 = (size_t)blockIdx.y * 128;
    int n0 = blockIdx.x * 128;
    int lm = tid >> 1, lk = (tid & 1) << 2;
    int ty = tid >> 4, tx = tid & 15;
    float acc[8][8] = {};
    float csc = g_cscale, dsc = g_dscale;
    for (int k0 = 0; k0 < NF; k0 += 8) {
        float4 a, b;
        if (k0 < DS) {
            a = *(const float4*)&g_W[(m0 + lm) * DS + k0 + lk];
            b = *(const float4*)&K21[(size_t)(n0 + lm) * DS + k0 + lk];
            b.x *= csc; b.y *= csc; b.z *= csc; b.w *= csc;
        } else {
            int kq = k0 - DS;
            a = *(const float4*)&u[(m0 + lm) * DI + kq + lk];
            b = *(const float4*)&K22[(size_t)(n0 + lm) * DI + kq + lk];
            b.x *= dsc; b.y *= dsc; b.z *= dsc; b.w *= dsc;
        }
        __syncthreads();
        As[lk+0][lm]=a.x; As[lk+1][lm]=a.y; As[lk+2][lm]=a.z; As[lk+3][lm]=a.w;
        Bs[lk+0][lm]=b.x; Bs[lk+1][lm]=b.y; Bs[lk+2][lm]=b.z; Bs[lk+3][lm]=b.w;
        __syncthreads();
#pragma unroll
        for (int kk = 0; kk < 8; kk++) {
            float4 a0 = *(const float4*)&As[kk][ty << 3];
            float4 a1 = *(const float4*)&As[kk][(ty << 3) + 4];
            float4 b0 = *(const float4*)&Bs[kk][tx << 3];
            float4 b1 = *(const float4*)&Bs[kk][(tx << 3) + 4];
            float Av[8] = {a0.x,a0.y,a0.z,a0.w,a1.x,a1.y,a1.z,a1.w};
            float Bv[8] = {b0.x,b0.y,b0.z,b0.w,b1.x,b1.y,b1.z,b1.w};
#pragma unroll
            for (int i = 0; i < 8; i++)
#pragma unroll
                for (int j = 0; j < 8; j++) acc[i][j] += Av[i] * Bv[j];
        }
    }
#pragma unroll
    for (int i = 0; i < 8; i++) {
        size_t row = m0 + (ty << 3) + i;
        float4 o0 = {acc[i][0], acc[i][1], acc[i][2], acc[i][3]};
        float4 o1 = {acc[i][4], acc[i][5], acc[i][6], acc[i][7]};
        *(float4*)&y[row * DO + n0 + (tx << 3)]     = o0;
        *(float4*)&y[row * DO + n0 + (tx << 3) + 4] = o1;
    }
}

extern "C" void kernel_launch(void* const* d_in, const int* in_sizes, int n_in,
                              void* d_out, int out_size) {
    const float* u         = (const float*)d_in[0];
    const float* rho_raw   = (const float*)d_in[1];
    const float* theta     = (const float*)d_in[2];
    const float* K12       = (const float*)d_in[3];
    const float* K21       = (const float*)d_in[4];
    const float* K22       = (const float*)d_in[5];
    const float* log_gamma = (const float*)d_in[6];
    float* y = (float*)d_out;

    build_kernel<<<(NF*NF + 255)/256, 256>>>(rho_raw, theta, K12, K21, K22);
    ktk_kernel<<<dim3(12,12), 256>>>();
    for (int k = 0; k < NSQ; k++) {
        trace_kernel<<<1, 1024>>>(k);
        sq_kernel<<<dim3(12,12), 256>>>(k);
    }
    finalize_kernel<<<1, 256>>>(rho_raw, theta, log_gamma);
    bu_gemm_kernel<<<dim3(DS/128, BT/128), 256>>>(u, K12);
    scan_kernel<<<dim3(NCHUNK, BATCH), NP>>>();
    carry_kernel<<<BATCH, NP>>>();
    fixup_kernel<<<dim3(NCHUNK, BATCH), NP>>>();
    y_gemm_kernel<<<dim3(DO/128, BT/128), 256>>>(u, K21, K22, y);
}